// round 12
// baseline (speedup 1.0000x reference)
#include <cuda_runtime.h>
#include <cstdint>

#define NN 100000
#define NE 3200000
#define F_IN 64
#define HID 16
#define NCLS 4

// ---------------- device scratch (static, no allocation) ----------------
__device__ float  g_deg[NN];      // weighted degree, then dinv (in place)
__device__ int    g_cnt[NN];      // in-degree counts
__device__ int    g_off[NN];      // CSR start offsets (exclusive scan of cnt)
__device__ int    g_cur[NN];      // fill cursors
__device__ int    g_src[NE];      // CSR: source node per edge (grouped by target)
__device__ float  g_w[NE];        // CSR: normalized weight per edge
__device__ float4 g_h[NN * 4];    // 16-wide features (h)
__device__ float4 g_a[NN * 4];    // 16-wide aggregate
__device__ float4 g_h3[NN];       // 4-wide h (layer 3)
__device__ float4 g_a3[NN];       // 4-wide aggregate

// ---------------- preprocessing ----------------
__global__ void gk_init() {
    int i = blockIdx.x * blockDim.x + threadIdx.x;
    if (i < NN) {
        g_deg[i] = 1.0f;   // self-loop weight
        g_cnt[i] = 0;
    }
}

// count in-edges per target + weighted degree (edge_index row 1 = targets)
__global__ void gk_count(const int* __restrict__ ei, const float* __restrict__ ew) {
    int e = blockIdx.x * blockDim.x + threadIdx.x;
    if (e >= NE) return;
    int c = ei[NE + e];
    atomicAdd(&g_cnt[c], 1);
    atomicAdd(&g_deg[c], ew[e]);
}

// single-block exclusive scan of g_cnt -> g_off, also copy to g_cur.
// Plain shared-memory Hillis-Steele (no shuffles).
__global__ void gk_scan() {
    __shared__ int s[1024];
    __shared__ int carry_s;
    int tid = threadIdx.x;
    if (tid == 0) carry_s = 0;
    __syncthreads();
    for (int base = 0; base < NN; base += 1024) {
        int i = base + tid;
        int v = (i < NN) ? g_cnt[i] : 0;
        s[tid] = v;
        __syncthreads();
        for (int d = 1; d < 1024; d <<= 1) {
            int t = (tid >= d) ? s[tid - d] : 0;
            __syncthreads();
            s[tid] += t;
            __syncthreads();
        }
        int incl = s[tid];
        int carry = carry_s;
        if (i < NN) {
            int ex = carry + incl - v;
            g_off[i] = ex;
            g_cur[i] = ex;
        }
        __syncthreads();
        if (tid == 1023) carry_s = carry + incl;
        __syncthreads();
    }
}

__global__ void gk_dinv() {
    int i = blockIdx.x * blockDim.x + threadIdx.x;
    if (i < NN) g_deg[i] = rsqrtf(g_deg[i]);   // deg >= 1 always
}

// fill CSR: for each edge, place (src, norm) into its target bucket
__global__ void gk_csr_fill(const int* __restrict__ ei, const float* __restrict__ ew) {
    int e = blockIdx.x * blockDim.x + threadIdx.x;
    if (e >= NE) return;
    int r = ei[e];
    int c = ei[NE + e];
    float w = g_deg[r] * ew[e] * g_deg[c];
    int pos = atomicAdd(&g_cur[c], 1);
    g_src[pos] = r;
    g_w[pos]   = w;
}

// ---------------- layer 1 matmul: h = x @ W1 ----------------
__global__ void gk_mm1(const float* __restrict__ x, const float* __restrict__ W) {
    __shared__ float sW[F_IN * HID];
    for (int i = threadIdx.x; i < F_IN * HID; i += blockDim.x) sW[i] = W[i];
    __syncthreads();
    int n = blockIdx.x * blockDim.x + threadIdx.x;
    if (n >= NN) return;

    float acc[HID];
#pragma unroll
    for (int j = 0; j < HID; j++) acc[j] = 0.0f;

    const float* xr = x + (size_t)n * F_IN;
#pragma unroll
    for (int k = 0; k < F_IN; k++) {
        float v = xr[k];
        const float* w = &sW[k * HID];
#pragma unroll
        for (int j = 0; j < HID; j++) acc[j] = fmaf(v, w[j], acc[j]);
    }
    float4* hp = g_h + n * 4;
#pragma unroll
    for (int q = 0; q < 4; q++)
        hp[q] = make_float4(acc[4 * q], acc[4 * q + 1], acc[4 * q + 2], acc[4 * q + 3]);
}

// ------------- middle matmul: h = relu(a + b_prev) @ W -------------
__global__ void gk_mm_mid(const float* __restrict__ W, const float* __restrict__ bprev) {
    __shared__ float sW[HID * HID];
    __shared__ float sb[HID];
    for (int i = threadIdx.x; i < HID * HID; i += blockDim.x) sW[i] = W[i];
    if (threadIdx.x < HID) sb[threadIdx.x] = bprev[threadIdx.x];
    __syncthreads();
    int n = blockIdx.x * blockDim.x + threadIdx.x;
    if (n >= NN) return;

    float in[HID];
    const float4* a4 = g_a + n * 4;
#pragma unroll
    for (int q = 0; q < 4; q++) {
        float4 v = a4[q];
        in[4 * q]     = fmaxf(v.x + sb[4 * q], 0.0f);
        in[4 * q + 1] = fmaxf(v.y + sb[4 * q + 1], 0.0f);
        in[4 * q + 2] = fmaxf(v.z + sb[4 * q + 2], 0.0f);
        in[4 * q + 3] = fmaxf(v.w + sb[4 * q + 3], 0.0f);
    }
    float acc[HID];
#pragma unroll
    for (int j = 0; j < HID; j++) acc[j] = 0.0f;
#pragma unroll
    for (int k = 0; k < HID; k++) {
#pragma unroll
        for (int j = 0; j < HID; j++) acc[j] = fmaf(in[k], sW[k * HID + j], acc[j]);
    }
    float4* hp = g_h + n * 4;
#pragma unroll
    for (int q = 0; q < 4; q++)
        hp[q] = make_float4(acc[4 * q], acc[4 * q + 1], acc[4 * q + 2], acc[4 * q + 3]);
}

// ------------- layer 3 matmul: h3 = relu(a + b3) @ W2 -------------
__global__ void gk_mm3(const float* __restrict__ W, const float* __restrict__ bprev) {
    __shared__ float sW[HID * NCLS];
    __shared__ float sb[HID];
    for (int i = threadIdx.x; i < HID * NCLS; i += blockDim.x) sW[i] = W[i];
    if (threadIdx.x < HID) sb[threadIdx.x] = bprev[threadIdx.x];
    __syncthreads();
    int n = blockIdx.x * blockDim.x + threadIdx.x;
    if (n >= NN) return;

    float in[HID];
    const float4* a4 = g_a + n * 4;
#pragma unroll
    for (int q = 0; q < 4; q++) {
        float4 v = a4[q];
        in[4 * q]     = fmaxf(v.x + sb[4 * q], 0.0f);
        in[4 * q + 1] = fmaxf(v.y + sb[4 * q + 1], 0.0f);
        in[4 * q + 2] = fmaxf(v.z + sb[4 * q + 2], 0.0f);
        in[4 * q + 3] = fmaxf(v.w + sb[4 * q + 3], 0.0f);
    }
    float acc[NCLS] = {0.f, 0.f, 0.f, 0.f};
#pragma unroll
    for (int k = 0; k < HID; k++) {
#pragma unroll
        for (int j = 0; j < NCLS; j++) acc[j] = fmaf(in[k], sW[k * NCLS + j], acc[j]);
    }
    g_h3[n] = make_float4(acc[0], acc[1], acc[2], acc[3]);
}

// ------------- CSR gather, 16-wide: a[n] = dinv^2*h[n] + sum_e w*h[src] -------------
// 4 threads per node; each thread owns one float4 slice of the 16 features.
// Quad lanes are warp-adjacent: edge loads broadcast, h loads coalesce to 64B.
__global__ void gk_agg16() {
    int gid = blockIdx.x * blockDim.x + threadIdx.x;
    int n = gid >> 2;
    int q = gid & 3;
    if (n >= NN) return;
    float s = g_deg[n]; s *= s;            // self-loop: dinv^2
    float4 acc = g_h[n * 4 + q];
    acc.x *= s; acc.y *= s; acc.z *= s; acc.w *= s;
    int st  = g_off[n];
    int cnt = g_cnt[n];
    for (int i = 0; i < cnt; i++) {
        int   src = g_src[st + i];
        float w   = g_w[st + i];
        float4 v  = g_h[src * 4 + q];
        acc.x = fmaf(w, v.x, acc.x);
        acc.y = fmaf(w, v.y, acc.y);
        acc.z = fmaf(w, v.z, acc.z);
        acc.w = fmaf(w, v.w, acc.w);
    }
    g_a[n * 4 + q] = acc;
}

// ------------- CSR gather, 4-wide (one thread per node) -------------
__global__ void gk_agg4() {
    int n = blockIdx.x * blockDim.x + threadIdx.x;
    if (n >= NN) return;
    float s = g_deg[n]; s *= s;
    float4 acc = g_h3[n];
    acc.x *= s; acc.y *= s; acc.z *= s; acc.w *= s;
    int st  = g_off[n];
    int cnt = g_cnt[n];
    for (int i = 0; i < cnt; i++) {
        int   src = g_src[st + i];
        float w   = g_w[st + i];
        float4 v  = g_h3[src];
        acc.x = fmaf(w, v.x, acc.x);
        acc.y = fmaf(w, v.y, acc.y);
        acc.z = fmaf(w, v.z, acc.z);
        acc.w = fmaf(w, v.w, acc.w);
    }
    g_a3[n] = acc;
}

// ------------- final: out = log_softmax(a3 + b2), scalar stores -------------
__global__ void gk_final(const float* __restrict__ b2, float* __restrict__ out) {
    int n = blockIdx.x * blockDim.x + threadIdx.x;
    if (n >= NN) return;
    float4 v = g_a3[n];
    float v0 = v.x + b2[0], v1 = v.y + b2[1], v2 = v.z + b2[2], v3 = v.w + b2[3];
    float m = fmaxf(fmaxf(v0, v1), fmaxf(v2, v3));
    float se = __expf(v0 - m) + __expf(v1 - m) + __expf(v2 - m) + __expf(v3 - m);
    float ls = m + __logf(se);
    float* o = out + (size_t)n * 4;
    o[0] = v0 - ls;
    o[1] = v1 - ls;
    o[2] = v2 - ls;
    o[3] = v3 - ls;
}

// ---------------- launch ----------------
extern "C" void kernel_launch(void* const* d_in, const int* in_sizes, int n_in,
                              void* d_out, int out_size) {
    const float* x   = (const float*)d_in[0];
    const int*   ei  = (const int*)d_in[1];     // int32! JAX x64 is disabled
    const float* ew  = (const float*)d_in[2];
    const float* W1  = (const float*)d_in[3];
    const float* b1  = (const float*)d_in[4];
    const float* W3  = (const float*)d_in[5];
    const float* b3  = (const float*)d_in[6];
    const float* W2  = (const float*)d_in[7];
    const float* b2  = (const float*)d_in[8];
    float* out = (float*)d_out;

    const int TB = 256;
    const int GN  = (NN + TB - 1) / TB;
    const int GE  = (NE + TB - 1) / TB;
    const int GN4 = (NN * 4 + TB - 1) / TB;

    // CSR build: counts+degree -> scan -> dinv -> bucket fill
    gk_init<<<GN, TB>>>();
    gk_count<<<GE, TB>>>(ei, ew);
    gk_scan<<<1, 1024>>>();
    gk_dinv<<<GN, TB>>>();
    gk_csr_fill<<<GE, TB>>>(ei, ew);

    // layer 1
    gk_mm1<<<GN, TB>>>(x, W1);
    gk_agg16<<<GN4, TB>>>();
    // layer 2
    gk_mm_mid<<<GN, TB>>>(W3, b1);
    gk_agg16<<<GN4, TB>>>();
    // layer 3
    gk_mm3<<<GN, TB>>>(W2, b3);
    gk_agg4<<<GN, TB>>>();
    // log_softmax epilogue
    gk_final<<<GN, TB>>>(b2, out);
}

// round 14
// speedup vs baseline: 1.7551x; 1.7551x over previous
#include <cuda_runtime.h>
#include <cstdint>

#define NN 100000
#define NE 3200000
#define F_IN 64
#define HID 16
#define NCLS 4

#define SCAN_B 1024
#define NBLK ((NN + SCAN_B - 1) / SCAN_B)   // 98

// ---------------- device scratch (static, no allocation) ----------------
__device__ float  g_deg[NN];      // weighted degree, then dinv (in place)
__device__ int    g_cnt[NN];      // in-degree counts
__device__ int    g_off[NN];      // CSR start offsets (exclusive scan of cnt)
__device__ int    g_cur[NN];      // fill cursors
__device__ int    g_bsum[NBLK];   // per-block sums (scan phase 1)
__device__ int    g_boff[NBLK];   // per-block offsets (scan phase 2)
__device__ int2   g_edge[NE];     // CSR: packed {src, w_bits} per edge, grouped by target
__device__ float4 g_h[NN * 4];    // 16-wide features (h)
__device__ float4 g_a[NN * 4];    // 16-wide aggregate
__device__ float4 g_h3[NN];       // 4-wide h (layer 3)
__device__ float4 g_a3[NN];       // 4-wide aggregate

// ---------------- preprocessing ----------------
__global__ void gk_init() {
    int i = blockIdx.x * blockDim.x + threadIdx.x;
    if (i < NN) {
        g_deg[i] = 1.0f;   // self-loop weight
        g_cnt[i] = 0;
    }
}

// count in-edges per target + weighted degree (edge_index row 1 = targets)
__global__ void gk_count(const int* __restrict__ ei, const float* __restrict__ ew) {
    int e = blockIdx.x * blockDim.x + threadIdx.x;
    if (e >= NE) return;
    int c = ei[NE + e];
    atomicAdd(&g_cnt[c], 1);
    atomicAdd(&g_deg[c], ew[e]);
}

// scan phase 1: per-block exclusive scan of g_cnt, block totals to g_bsum
__global__ void gk_scan1() {
    __shared__ int s[SCAN_B];
    int tid = threadIdx.x;
    int i = blockIdx.x * SCAN_B + tid;
    int v = (i < NN) ? g_cnt[i] : 0;
    s[tid] = v;
    __syncthreads();
#pragma unroll
    for (int d = 1; d < SCAN_B; d <<= 1) {
        int t = (tid >= d) ? s[tid - d] : 0;
        __syncthreads();
        s[tid] += t;
        __syncthreads();
    }
    if (i < NN) g_off[i] = s[tid] - v;          // block-local exclusive
    if (tid == SCAN_B - 1) g_bsum[blockIdx.x] = s[tid];
}

// scan phase 2: exclusive scan of NBLK block sums (single small block)
__global__ void gk_scan2() {
    __shared__ int s[128];
    int tid = threadIdx.x;
    int v = (tid < NBLK) ? g_bsum[tid] : 0;
    s[tid] = v;
    __syncthreads();
#pragma unroll
    for (int d = 1; d < 128; d <<= 1) {
        int t = (tid >= d) ? s[tid - d] : 0;
        __syncthreads();
        s[tid] += t;
        __syncthreads();
    }
    if (tid < NBLK) g_boff[tid] = s[tid] - v;
}

// scan phase 3: add block offsets, init cursors; fused dinv
__global__ void gk_scan3() {
    int i = blockIdx.x * blockDim.x + threadIdx.x;
    if (i >= NN) return;
    int off = g_off[i] + g_boff[i >> 10];
    g_off[i] = off;
    g_cur[i] = off;
    g_deg[i] = rsqrtf(g_deg[i]);   // deg >= 1 always
}

// fill CSR: for each edge, place packed {src, norm} into its target bucket
__global__ void gk_csr_fill(const int* __restrict__ ei, const float* __restrict__ ew) {
    int e = blockIdx.x * blockDim.x + threadIdx.x;
    if (e >= NE) return;
    int r = ei[e];
    int c = ei[NE + e];
    float w = g_deg[r] * ew[e] * g_deg[c];
    int pos = atomicAdd(&g_cur[c], 1);
    g_edge[pos] = make_int2(r, __float_as_int(w));
}

// ---------------- layer 1 matmul: h = x @ W1 ----------------
__global__ void gk_mm1(const float* __restrict__ x, const float* __restrict__ W) {
    __shared__ float sW[F_IN * HID];
    for (int i = threadIdx.x; i < F_IN * HID; i += blockDim.x) sW[i] = W[i];
    __syncthreads();
    int n = blockIdx.x * blockDim.x + threadIdx.x;
    if (n >= NN) return;

    float acc[HID];
#pragma unroll
    for (int j = 0; j < HID; j++) acc[j] = 0.0f;

    const float* xr = x + (size_t)n * F_IN;
#pragma unroll
    for (int k = 0; k < F_IN; k++) {
        float v = xr[k];
        const float* w = &sW[k * HID];
#pragma unroll
        for (int j = 0; j < HID; j++) acc[j] = fmaf(v, w[j], acc[j]);
    }
    float4* hp = g_h + n * 4;
#pragma unroll
    for (int q = 0; q < 4; q++)
        hp[q] = make_float4(acc[4 * q], acc[4 * q + 1], acc[4 * q + 2], acc[4 * q + 3]);
}

// ------------- middle matmul: h = relu(a + b_prev) @ W -------------
__global__ void gk_mm_mid(const float* __restrict__ W, const float* __restrict__ bprev) {
    __shared__ float sW[HID * HID];
    __shared__ float sb[HID];
    for (int i = threadIdx.x; i < HID * HID; i += blockDim.x) sW[i] = W[i];
    if (threadIdx.x < HID) sb[threadIdx.x] = bprev[threadIdx.x];
    __syncthreads();
    int n = blockIdx.x * blockDim.x + threadIdx.x;
    if (n >= NN) return;

    float in[HID];
    const float4* a4 = g_a + n * 4;
#pragma unroll
    for (int q = 0; q < 4; q++) {
        float4 v = a4[q];
        in[4 * q]     = fmaxf(v.x + sb[4 * q], 0.0f);
        in[4 * q + 1] = fmaxf(v.y + sb[4 * q + 1], 0.0f);
        in[4 * q + 2] = fmaxf(v.z + sb[4 * q + 2], 0.0f);
        in[4 * q + 3] = fmaxf(v.w + sb[4 * q + 3], 0.0f);
    }
    float acc[HID];
#pragma unroll
    for (int j = 0; j < HID; j++) acc[j] = 0.0f;
#pragma unroll
    for (int k = 0; k < HID; k++) {
#pragma unroll
        for (int j = 0; j < HID; j++) acc[j] = fmaf(in[k], sW[k * HID + j], acc[j]);
    }
    float4* hp = g_h + n * 4;
#pragma unroll
    for (int q = 0; q < 4; q++)
        hp[q] = make_float4(acc[4 * q], acc[4 * q + 1], acc[4 * q + 2], acc[4 * q + 3]);
}

// ------------- layer 3 matmul: h3 = relu(a + b3) @ W2 -------------
__global__ void gk_mm3(const float* __restrict__ W, const float* __restrict__ bprev) {
    __shared__ float sW[HID * NCLS];
    __shared__ float sb[HID];
    for (int i = threadIdx.x; i < HID * NCLS; i += blockDim.x) sW[i] = W[i];
    if (threadIdx.x < HID) sb[threadIdx.x] = bprev[threadIdx.x];
    __syncthreads();
    int n = blockIdx.x * blockDim.x + threadIdx.x;
    if (n >= NN) return;

    float in[HID];
    const float4* a4 = g_a + n * 4;
#pragma unroll
    for (int q = 0; q < 4; q++) {
        float4 v = a4[q];
        in[4 * q]     = fmaxf(v.x + sb[4 * q], 0.0f);
        in[4 * q + 1] = fmaxf(v.y + sb[4 * q + 1], 0.0f);
        in[4 * q + 2] = fmaxf(v.z + sb[4 * q + 2], 0.0f);
        in[4 * q + 3] = fmaxf(v.w + sb[4 * q + 3], 0.0f);
    }
    float acc[NCLS] = {0.f, 0.f, 0.f, 0.f};
#pragma unroll
    for (int k = 0; k < HID; k++) {
#pragma unroll
        for (int j = 0; j < NCLS; j++) acc[j] = fmaf(in[k], sW[k * NCLS + j], acc[j]);
    }
    g_h3[n] = make_float4(acc[0], acc[1], acc[2], acc[3]);
}

// ------------- CSR gather, 16-wide: a[n] = dinv^2*h[n] + sum_e w*h[src] -------------
// 4 threads per node; each thread owns one float4 slice of the 16 features.
// Packed 8B edge record broadcasts across the quad; unroll x2 for MLP.
__global__ void gk_agg16() {
    int gid = blockIdx.x * blockDim.x + threadIdx.x;
    int n = gid >> 2;
    int q = gid & 3;
    if (n >= NN) return;
    float s = g_deg[n]; s *= s;            // self-loop: dinv^2
    float4 acc = g_h[n * 4 + q];
    acc.x *= s; acc.y *= s; acc.z *= s; acc.w *= s;
    int st  = g_off[n];
    int cnt = g_cnt[n];
    int i = 0;
    for (; i + 2 <= cnt; i += 2) {
        int2 e0 = g_edge[st + i];
        int2 e1 = g_edge[st + i + 1];
        float4 v0 = g_h[e0.x * 4 + q];
        float4 v1 = g_h[e1.x * 4 + q];
        float w0 = __int_as_float(e0.y);
        float w1 = __int_as_float(e1.y);
        acc.x = fmaf(w0, v0.x, acc.x);
        acc.y = fmaf(w0, v0.y, acc.y);
        acc.z = fmaf(w0, v0.z, acc.z);
        acc.w = fmaf(w0, v0.w, acc.w);
        acc.x = fmaf(w1, v1.x, acc.x);
        acc.y = fmaf(w1, v1.y, acc.y);
        acc.z = fmaf(w1, v1.z, acc.z);
        acc.w = fmaf(w1, v1.w, acc.w);
    }
    if (i < cnt) {
        int2 e0 = g_edge[st + i];
        float4 v0 = g_h[e0.x * 4 + q];
        float w0 = __int_as_float(e0.y);
        acc.x = fmaf(w0, v0.x, acc.x);
        acc.y = fmaf(w0, v0.y, acc.y);
        acc.z = fmaf(w0, v0.z, acc.z);
        acc.w = fmaf(w0, v0.w, acc.w);
    }
    g_a[n * 4 + q] = acc;
}

// ------------- CSR gather, 4-wide (one thread per node) -------------
__global__ void gk_agg4() {
    int n = blockIdx.x * blockDim.x + threadIdx.x;
    if (n >= NN) return;
    float s = g_deg[n]; s *= s;
    float4 acc = g_h3[n];
    acc.x *= s; acc.y *= s; acc.z *= s; acc.w *= s;
    int st  = g_off[n];
    int cnt = g_cnt[n];
    for (int i = 0; i < cnt; i++) {
        int2 e0 = g_edge[st + i];
        float w = __int_as_float(e0.y);
        float4 v = g_h3[e0.x];
        acc.x = fmaf(w, v.x, acc.x);
        acc.y = fmaf(w, v.y, acc.y);
        acc.z = fmaf(w, v.z, acc.z);
        acc.w = fmaf(w, v.w, acc.w);
    }
    g_a3[n] = acc;
}

// ------------- final: out = log_softmax(a3 + b2), scalar stores -------------
__global__ void gk_final(const float* __restrict__ b2, float* __restrict__ out) {
    int n = blockIdx.x * blockDim.x + threadIdx.x;
    if (n >= NN) return;
    float4 v = g_a3[n];
    float v0 = v.x + b2[0], v1 = v.y + b2[1], v2 = v.z + b2[2], v3 = v.w + b2[3];
    float m = fmaxf(fmaxf(v0, v1), fmaxf(v2, v3));
    float se = __expf(v0 - m) + __expf(v1 - m) + __expf(v2 - m) + __expf(v3 - m);
    float ls = m + __logf(se);
    float* o = out + (size_t)n * 4;
    o[0] = v0 - ls;
    o[1] = v1 - ls;
    o[2] = v2 - ls;
    o[3] = v3 - ls;
}

// ---------------- launch ----------------
extern "C" void kernel_launch(void* const* d_in, const int* in_sizes, int n_in,
                              void* d_out, int out_size) {
    const float* x   = (const float*)d_in[0];
    const int*   ei  = (const int*)d_in[1];     // int32 (JAX x64 disabled)
    const float* ew  = (const float*)d_in[2];
    const float* W1  = (const float*)d_in[3];
    const float* b1  = (const float*)d_in[4];
    const float* W3  = (const float*)d_in[5];
    const float* b3  = (const float*)d_in[6];
    const float* W2  = (const float*)d_in[7];
    const float* b2  = (const float*)d_in[8];
    float* out = (float*)d_out;

    const int TB = 256;
    const int GN  = (NN + TB - 1) / TB;
    const int GE  = (NE + TB - 1) / TB;
    const int GN4 = (NN * 4 + TB - 1) / TB;

    // CSR build: counts+degree -> 3-phase parallel scan (dinv fused) -> bucket fill
    gk_init<<<GN, TB>>>();
    gk_count<<<GE, TB>>>(ei, ew);
    gk_scan1<<<NBLK, SCAN_B>>>();
    gk_scan2<<<1, 128>>>();
    gk_scan3<<<GN, TB>>>();
    gk_csr_fill<<<GE, TB>>>(ei, ew);

    // layer 1
    gk_mm1<<<GN, TB>>>(x, W1);
    gk_agg16<<<GN4, TB>>>();
    // layer 2
    gk_mm_mid<<<GN, TB>>>(W3, b1);
    gk_agg16<<<GN4, TB>>>();
    // layer 3
    gk_mm3<<<GN, TB>>>(W2, b3);
    gk_agg4<<<GN, TB>>>();
    // log_softmax epilogue
    gk_final<<<GN, TB>>>(b2, out);
}